// round 11
// baseline (speedup 1.0000x reference)
#include <cuda_runtime.h>

#define GS      256
#define PARAM   128
#define I1      64
#define I2      32
#define PK      96
#define KC      32
#define BATCH   4
#define NROWS   (BATCH * GS)   // 1024
#define EPS     1e-3f

#define M2_PAD  68             // padded row length for sM2T[i][j]
#define M3_PAD  36             // padded row length for sM3T[k][i]
#define MAXP    48             // per-row cap on stored nonzeros (mean 16, 8 sigma)
#define RPB     4              // rows per block
#define GROUP   4              // pairs per warp-group (weight-load amortization)
#define TOTP    128            // cap on padded pairs per block (mean ~76, ~6.7 sigma)

// Dynamic smem layout (floats): [ sM2T | sM3T | sH1 ]
#define DYN_M2T_OFF  0
#define DYN_M3T_OFF  (I2 * M2_PAD)                    // 2176
#define DYN_H1_OFF   (DYN_M3T_OFF + PK * M3_PAD)      // 2176+3456 = 5632
#define DYN_FLOATS   (DYN_H1_OFF + TOTP * I1)         // 5632+8192 = 13824
#define DYN_BYTES    (DYN_FLOATS * 4)                 // 55296 B

// Scratch (allocation-free rule: __device__ globals). 16B-aligned for float4 access.
__device__ __align__(16) float g_A[NROWS * I1];     // folded A'' (BN1 affine applied)
__device__ __align__(16) float g_C[NROWS * I1];     // C' = val@M1bot * sg1
__device__ __align__(16) float g_M2T[I2 * M2_PAD];  // BN2-folded, transposed: [i][j]
__device__ __align__(16) float g_M3T[PK * M3_PAD];  // BN3-folded, transposed: [k][i]
__device__ float g_c2[I2];
__device__ float g_c3[PK];

// ---------------------------------------------------------------------------
// Kernel 1: precompute A''/C' for 4 rows per block (blocks 0..255)
//           + one extra block (256) folding BN2/BN3 into transposed weights
// ---------------------------------------------------------------------------
__global__ __launch_bounds__(256) void precompute_kernel(
    const float* __restrict__ val,
    const float* __restrict__ M1,   // (2*PARAM, I1) row-major
    const float* __restrict__ B1,
    const float* __restrict__ g1, const float* __restrict__ b1,
    const float* __restrict__ m1, const float* __restrict__ v1,
    const float* __restrict__ M2,  const float* __restrict__ B2,
    const float* __restrict__ M3,  const float* __restrict__ B3,
    const float* __restrict__ g2,  const float* __restrict__ b2,
    const float* __restrict__ m2,  const float* __restrict__ v2,
    const float* __restrict__ g3,  const float* __restrict__ b3,
    const float* __restrict__ m3,  const float* __restrict__ v3)
{
    const int tid = threadIdx.x;

    if (blockIdx.x == NROWS / RPB) {
        __shared__ float sg2[I2], sg3[PK];
        if (tid < I2) {
            const float s = g2[tid] * rsqrtf(v2[tid] + EPS);
            sg2[tid] = s;
            g_c2[tid] = (B2[tid] - m2[tid]) * s + b2[tid];
        }
        if (tid < PK) {
            const float s = g3[tid] * rsqrtf(v3[tid] + EPS);
            sg3[tid] = s;
            g_c3[tid] = (B3[tid] - m3[tid]) * s + b3[tid];
        }
        __syncthreads();
        for (int idx = tid; idx < I2 * I1; idx += 256) {
            const int i  = idx >> 6;
            const int jj = idx & 63;
            g_M2T[i * M2_PAD + jj] = M2[jj * I2 + i] * sg2[i];
        }
        for (int idx = tid; idx < PK * I2; idx += 256) {
            const int k = idx >> 5;
            const int i = idx & 31;
            g_M3T[k * M3_PAD + i] = M3[i * PK + k] * sg3[k];
        }
        return;
    }

    __shared__ float sval[RPB][PARAM];
    const int row0 = blockIdx.x * RPB;
    for (int idx = tid; idx < RPB * PARAM; idx += 256)
        sval[idx >> 7][idx & 127] = val[row0 * PARAM + idx];
    __syncthreads();

    const int r = tid >> 6;          // 0..3 local row
    const int j = tid & 63;          // 0..63 channel
    float accT = 0.f, accB = 0.f;
    #pragma unroll 8
    for (int p = 0; p < PARAM; ++p) {
        const float v = sval[r][p];
        accT = fmaf(v, M1[p * I1 + j],           accT);
        accB = fmaf(v, M1[(PARAM + p) * I1 + j], accB);
    }
    const float sg = g1[j] * rsqrtf(v1[j] + EPS);
    const int row = row0 + r;
    g_A[row * I1 + j] = (accT - accB) * sg + (B1[j] - m1[j]) * sg + b1[j];
    g_C[row * I1 + j] = accB * sg;
}

// ---------------------------------------------------------------------------
// Kernel 2: sparse pair MLP. One block per 4 rows, 256 threads.
// Flat, row-pure group list for the whole block; all 8 warps stride over it.
// ---------------------------------------------------------------------------
__global__ __launch_bounds__(256, 2) void pair_kernel(
    const float* __restrict__ mat, const float* __restrict__ val,
    float* __restrict__ out)
{
    extern __shared__ __align__(16) float dyn[];
    float* sM2T = dyn + DYN_M2T_OFF;            // [I2][M2_PAD]
    float* sM3T = dyn + DYN_M3T_OFF;            // [PK][M3_PAD]
    float* sH1  = dyn + DYN_H1_OFF;             // [TOTP][I1]

    __shared__ __align__(16) float sH2[8][GROUP][I2];
    __shared__ float c2s[I2], c3s[PK];
    __shared__ float sA[RPB][I1];
    __shared__ float sSum[RPB][PK];
    __shared__ int   sY[RPB][MAXP];
    __shared__ float sW[RPB][MAXP];
    __shared__ int   sCnt[RPB];
    __shared__ float sPW[TOTP];                 // padded per-pair weights (0 for pad)
    __shared__ int   sGrpRow[TOTP / GROUP];
    __shared__ int   sOff[RPB], sCc[RPB];
    __shared__ int   sTot, sNG;

    const int tid  = threadIdx.x;
    const int warp = tid >> 5;
    const int lane = tid & 31;
    const int row0 = blockIdx.x * RPB;
    const int b    = row0 >> 8;

    // --- prologue: float4 copies of pre-folded weights ---
    {
        const float4* s2 = (const float4*)g_M2T;
        float4*       d2 = (float4*)sM2T;
        for (int i = tid; i < (I2 * M2_PAD) / 4; i += 256) d2[i] = s2[i];
        const float4* s3 = (const float4*)g_M3T;
        float4*       d3 = (float4*)sM3T;
        for (int i = tid; i < (PK * M3_PAD) / 4; i += 256) d3[i] = s3[i];
    }
    if (tid < I2) c2s[tid] = g_c2[tid];
    if (tid < PK) c3s[tid] = g_c3[tid];
    for (int idx = tid; idx < RPB * I1; idx += 256)
        sA[idx >> 6][idx & 63] = g_A[(row0 + (idx >> 6)) * I1 + (idx & 63)];
    for (int idx = tid; idx < RPB * PK; idx += 256)
        sSum[idx / PK][idx % PK] = 0.f;
    if (tid < RPB) sCnt[tid] = 0;
    __syncthreads();

    // --- compact nonzeros of the 4 mat rows ---
    {
        const float* mbase = mat + row0 * GS;
        #pragma unroll
        for (int e = tid; e < RPB * GS; e += 256) {
            const float w = mbase[e];
            if (w != 0.f) {
                const int r = e >> 8;
                const int y = e & 255;
                const int idx = atomicAdd(&sCnt[r], 1);
                if (idx < MAXP) { sY[r][idx] = y; sW[r][idx] = w; }
            }
        }
    }
    __syncthreads();

    // --- metadata: padded row-pure layout + group->row map (thread 0) ---
    if (tid == 0) {
        int off = 0;
        #pragma unroll
        for (int r = 0; r < RPB; ++r) {
            int c  = min(sCnt[r], MAXP);
            int pc = (c + GROUP - 1) & ~(GROUP - 1);
            if (off + pc > TOTP) pc = TOTP - off;   // both multiples of 4
            if (c > pc) c = pc;
            sOff[r] = off; sCc[r] = c;
            for (int g = 0; g < pc / GROUP; ++g)
                sGrpRow[(off >> 2) + g] = r;
            off += pc;
        }
        sTot = off;
        sNG  = off >> 2;
    }
    __syncthreads();

    // --- build ALL h1 vectors + padded weights in one phase ---
    const int tot = sTot;
    for (int idx = tid; idx < tot * I1; idx += 256) {
        const int p = idx >> 6;
        const int j = idx & 63;
        const int r = (p >= sOff[1]) + (p >= sOff[2]) + (p >= sOff[3]);
        const int lp = p - sOff[r];
        const int y = (lp < sCc[r]) ? sY[r][lp] : 0;
        sH1[p * I1 + j] = fmaxf(sA[r][j] + g_C[(b * GS + y) * I1 + j], 0.f);
        if (j == 0) sPW[p] = (lp < sCc[r]) ? sW[r][lp] : 0.f;
    }
    __syncthreads();

    // --- mainloop: warps stride over ALL groups; flush accs on row change ---
    const int nG = sNG;
    float acc0 = 0.f, acc1 = 0.f, acc2 = 0.f;
    int curR = -1;

    for (int g = warp; g < nG; g += 8) {
        const int r = sGrpRow[g];
        if (r != curR) {
            if (curR >= 0) {
                atomicAdd(&sSum[curR][lane],      acc0);
                atomicAdd(&sSum[curR][lane + 32], acc1);
                atomicAdd(&sSum[curR][lane + 64], acc2);
            }
            curR = r;
            acc0 = acc1 = acc2 = 0.f;
        }
        const int p0 = g * GROUP;

        // ---- h2 for 4 pairs: each weight float4 loaded once ----
        float h0a = c2s[lane], h1a = h0a, h2a = h0a, h3a = h0a;
        const float4* wv = (const float4*)(sM2T + lane * M2_PAD);
        const float4* v0 = (const float4*)(sH1 + (p0 + 0) * I1);
        const float4* v1 = (const float4*)(sH1 + (p0 + 1) * I1);
        const float4* v2 = (const float4*)(sH1 + (p0 + 2) * I1);
        const float4* v3 = (const float4*)(sH1 + (p0 + 3) * I1);
        #pragma unroll
        for (int q = 0; q < I1 / 4; ++q) {
            const float4 w = wv[q];
            const float4 a = v0[q];
            const float4 bb = v1[q];
            const float4 c = v2[q];
            const float4 d = v3[q];
            h0a = fmaf(a.x,  w.x, h0a); h0a = fmaf(a.y,  w.y, h0a);
            h0a = fmaf(a.z,  w.z, h0a); h0a = fmaf(a.w,  w.w, h0a);
            h1a = fmaf(bb.x, w.x, h1a); h1a = fmaf(bb.y, w.y, h1a);
            h1a = fmaf(bb.z, w.z, h1a); h1a = fmaf(bb.w, w.w, h1a);
            h2a = fmaf(c.x,  w.x, h2a); h2a = fmaf(c.y,  w.y, h2a);
            h2a = fmaf(c.z,  w.z, h2a); h2a = fmaf(c.w,  w.w, h2a);
            h3a = fmaf(d.x,  w.x, h3a); h3a = fmaf(d.y,  w.y, h3a);
            h3a = fmaf(d.z,  w.z, h3a); h3a = fmaf(d.w,  w.w, h3a);
        }
        sH2[warp][0][lane] = fmaxf(h0a, 0.f);
        sH2[warp][1][lane] = fmaxf(h1a, 0.f);
        sH2[warp][2][lane] = fmaxf(h2a, 0.f);
        sH2[warp][3][lane] = fmaxf(h3a, 0.f);
        __syncwarp();

        // ---- h3 for 4 pairs x 3 k-slices ----
        float t00 = c3s[lane], t01 = t00, t02 = t00, t03 = t00;
        float t10 = c3s[lane + 32], t11 = t10, t12 = t10, t13 = t10;
        float t20 = c3s[lane + 64], t21 = t20, t22 = t20, t23 = t20;
        const float4* w0 = (const float4*)(sM3T + lane * M3_PAD);
        const float4* w1 = (const float4*)(sM3T + (lane + 32) * M3_PAD);
        const float4* w2 = (const float4*)(sM3T + (lane + 64) * M3_PAD);
        const float4* u0 = (const float4*)sH2[warp][0];
        const float4* u1 = (const float4*)sH2[warp][1];
        const float4* u2 = (const float4*)sH2[warp][2];
        const float4* u3 = (const float4*)sH2[warp][3];
        #pragma unroll
        for (int q = 0; q < I2 / 4; ++q) {
            const float4 a = w0[q];
            const float4 c = w1[q];
            const float4 d = w2[q];
            const float4 h0 = u0[q];
            const float4 h1 = u1[q];
            const float4 h2 = u2[q];
            const float4 h3 = u3[q];
            t00 = fmaf(h0.x, a.x, t00); t00 = fmaf(h0.y, a.y, t00);
            t00 = fmaf(h0.z, a.z, t00); t00 = fmaf(h0.w, a.w, t00);
            t01 = fmaf(h1.x, a.x, t01); t01 = fmaf(h1.y, a.y, t01);
            t01 = fmaf(h1.z, a.z, t01); t01 = fmaf(h1.w, a.w, t01);
            t02 = fmaf(h2.x, a.x, t02); t02 = fmaf(h2.y, a.y, t02);
            t02 = fmaf(h2.z, a.z, t02); t02 = fmaf(h2.w, a.w, t02);
            t03 = fmaf(h3.x, a.x, t03); t03 = fmaf(h3.y, a.y, t03);
            t03 = fmaf(h3.z, a.z, t03); t03 = fmaf(h3.w, a.w, t03);
            t10 = fmaf(h0.x, c.x, t10); t10 = fmaf(h0.y, c.y, t10);
            t10 = fmaf(h0.z, c.z, t10); t10 = fmaf(h0.w, c.w, t10);
            t11 = fmaf(h1.x, c.x, t11); t11 = fmaf(h1.y, c.y, t11);
            t11 = fmaf(h1.z, c.z, t11); t11 = fmaf(h1.w, c.w, t11);
            t12 = fmaf(h2.x, c.x, t12); t12 = fmaf(h2.y, c.y, t12);
            t12 = fmaf(h2.z, c.z, t12); t12 = fmaf(h2.w, c.w, t12);
            t13 = fmaf(h3.x, c.x, t13); t13 = fmaf(h3.y, c.y, t13);
            t13 = fmaf(h3.z, c.z, t13); t13 = fmaf(h3.w, c.w, t13);
            t20 = fmaf(h0.x, d.x, t20); t20 = fmaf(h0.y, d.y, t20);
            t20 = fmaf(h0.z, d.z, t20); t20 = fmaf(h0.w, d.w, t20);
            t21 = fmaf(h1.x, d.x, t21); t21 = fmaf(h1.y, d.y, t21);
            t21 = fmaf(h1.z, d.z, t21); t21 = fmaf(h1.w, d.w, t21);
            t22 = fmaf(h2.x, d.x, t22); t22 = fmaf(h2.y, d.y, t22);
            t22 = fmaf(h2.z, d.z, t22); t22 = fmaf(h2.w, d.w, t22);
            t23 = fmaf(h3.x, d.x, t23); t23 = fmaf(h3.y, d.y, t23);
            t23 = fmaf(h3.z, d.z, t23); t23 = fmaf(h3.w, d.w, t23);
        }
        const float wg0 = sPW[p0 + 0];
        const float wg1 = sPW[p0 + 1];
        const float wg2 = sPW[p0 + 2];
        const float wg3 = sPW[p0 + 3];
        acc0 = fmaf(wg0, fmaxf(t00, 0.f), acc0);
        acc0 = fmaf(wg1, fmaxf(t01, 0.f), acc0);
        acc0 = fmaf(wg2, fmaxf(t02, 0.f), acc0);
        acc0 = fmaf(wg3, fmaxf(t03, 0.f), acc0);
        acc1 = fmaf(wg0, fmaxf(t10, 0.f), acc1);
        acc1 = fmaf(wg1, fmaxf(t11, 0.f), acc1);
        acc1 = fmaf(wg2, fmaxf(t12, 0.f), acc1);
        acc1 = fmaf(wg3, fmaxf(t13, 0.f), acc1);
        acc2 = fmaf(wg0, fmaxf(t20, 0.f), acc2);
        acc2 = fmaf(wg1, fmaxf(t21, 0.f), acc2);
        acc2 = fmaf(wg2, fmaxf(t22, 0.f), acc2);
        acc2 = fmaf(wg3, fmaxf(t23, 0.f), acc2);
        __syncwarp();   // protect sH2[warp] before next group's write
    }
    if (curR >= 0) {
        atomicAdd(&sSum[curR][lane],      acc0);
        atomicAdd(&sSum[curR][lane + 32], acc1);
        atomicAdd(&sSum[curR][lane + 64], acc2);
    }
    __syncthreads();

    // --- output: 4 rows x [con(32) | clip(sum/16)(96)] ---
    for (int idx = tid; idx < RPB * PARAM; idx += 256) {
        const int r = idx >> 7;
        const int k = idx & 127;
        const int row = row0 + r;
        float o;
        if (k < KC) o = val[row * PARAM + k];
        else {
            const float s = sSum[r][k - KC] * (1.0f / 16.0f);
            o = fminf(fmaxf(s, -1.f), 1.f);
        }
        out[row * PARAM + k] = o;
    }
}

// ---------------------------------------------------------------------------
extern "C" void kernel_launch(void* const* d_in, const int* in_sizes, int n_in,
                              void* d_out, int out_size)
{
    const float* mat = (const float*)d_in[0];
    const float* val = (const float*)d_in[1];
    const float* M1  = (const float*)d_in[2];
    const float* B1  = (const float*)d_in[3];
    const float* M2  = (const float*)d_in[4];
    const float* B2  = (const float*)d_in[5];
    const float* M3  = (const float*)d_in[6];
    const float* B3  = (const float*)d_in[7];
    const float* g1  = (const float*)d_in[8];
    const float* b1  = (const float*)d_in[9];
    const float* m1  = (const float*)d_in[10];
    const float* v1  = (const float*)d_in[11];
    const float* g2  = (const float*)d_in[12];
    const float* b2  = (const float*)d_in[13];
    const float* m2  = (const float*)d_in[14];
    const float* v2  = (const float*)d_in[15];
    const float* g3  = (const float*)d_in[16];
    const float* b3  = (const float*)d_in[17];
    const float* m3  = (const float*)d_in[18];
    const float* v3  = (const float*)d_in[19];
    float* out = (float*)d_out;

    static int configured = 0;
    if (!configured) {
        cudaFuncSetAttribute(pair_kernel,
                             cudaFuncAttributeMaxDynamicSharedMemorySize,
                             DYN_BYTES);
        configured = 1;
    }

    precompute_kernel<<<NROWS / RPB + 1, 256>>>(val, M1, B1, g1, b1, m1, v1,
                                                M2, B2, M3, B3,
                                                g2, b2, m2, v2, g3, b3, m3, v3);
    pair_kernel<<<NROWS / RPB, 256, DYN_BYTES>>>(mat, val, out);
}

// round 12
// speedup vs baseline: 1.5575x; 1.5575x over previous
#include <cuda_runtime.h>

#define GS      256
#define PARAM   128
#define I1      64
#define I2      32
#define PK      96
#define KC      32
#define BATCH   4
#define NROWS   (BATCH * GS)   // 1024
#define EPS     1e-3f

#define M2_PAD  68             // padded row length for sM2T[i][j]
#define M3_PAD  36             // padded row length for sM3T[k][i]
#define MAXP    48             // per-row cap on stored nonzeros (mean 16, 8 sigma)
#define RPB     4              // rows per block
#define GROUP   4              // pairs per warp-group (weight-load amortization)
#define TOTP    128            // cap on padded pairs per block (needs cnt>116 = 6.7 sigma)

// Dynamic smem layout (floats): [ sM2T | sM3T | sH1 ]
#define DYN_M2T_OFF  0
#define DYN_M3T_OFF  (I2 * M2_PAD)                    // 2176
#define DYN_H1_OFF   (DYN_M3T_OFF + PK * M3_PAD)      // 5632
#define DYN_FLOATS   (DYN_H1_OFF + TOTP * I1)         // 13824
#define DYN_BYTES    (DYN_FLOATS * 4)                 // 55296 B

// Scratch (allocation-free rule: __device__ globals). 16B-aligned for float4 access.
__device__ __align__(16) float g_A[NROWS * I1];     // folded A'' (BN1 affine applied)
__device__ __align__(16) float g_C[NROWS * I1];     // C' = val@M1bot * sg1
__device__ __align__(16) float g_M2T[I2 * M2_PAD];  // BN2-folded, transposed: [i][j]
__device__ __align__(16) float g_M3T[PK * M3_PAD];  // BN3-folded, transposed: [k][i]
__device__ float g_c2[I2];
__device__ float g_c3[PK];

// ---------------------------------------------------------------------------
// Kernel 1: precompute A''/C' for 4 rows per block (blocks 0..255)
//           + one extra block (256) folding BN2/BN3 into transposed weights
// ---------------------------------------------------------------------------
__global__ __launch_bounds__(256) void precompute_kernel(
    const float* __restrict__ val,
    const float* __restrict__ M1,   // (2*PARAM, I1) row-major
    const float* __restrict__ B1,
    const float* __restrict__ g1, const float* __restrict__ b1,
    const float* __restrict__ m1, const float* __restrict__ v1,
    const float* __restrict__ M2,  const float* __restrict__ B2,
    const float* __restrict__ M3,  const float* __restrict__ B3,
    const float* __restrict__ g2,  const float* __restrict__ b2,
    const float* __restrict__ m2,  const float* __restrict__ v2,
    const float* __restrict__ g3,  const float* __restrict__ b3,
    const float* __restrict__ m3,  const float* __restrict__ v3)
{
    const int tid = threadIdx.x;

    if (blockIdx.x == NROWS / RPB) {
        __shared__ float sg2[I2], sg3[PK];
        if (tid < I2) {
            const float s = g2[tid] * rsqrtf(v2[tid] + EPS);
            sg2[tid] = s;
            g_c2[tid] = (B2[tid] - m2[tid]) * s + b2[tid];
        }
        if (tid < PK) {
            const float s = g3[tid] * rsqrtf(v3[tid] + EPS);
            sg3[tid] = s;
            g_c3[tid] = (B3[tid] - m3[tid]) * s + b3[tid];
        }
        __syncthreads();
        for (int idx = tid; idx < I2 * I1; idx += 256) {
            const int i  = idx >> 6;
            const int jj = idx & 63;
            g_M2T[i * M2_PAD + jj] = M2[jj * I2 + i] * sg2[i];
        }
        for (int idx = tid; idx < PK * I2; idx += 256) {
            const int k = idx >> 5;
            const int i = idx & 31;
            g_M3T[k * M3_PAD + i] = M3[i * PK + k] * sg3[k];
        }
        return;
    }

    __shared__ float sval[RPB][PARAM];
    const int row0 = blockIdx.x * RPB;
    for (int idx = tid; idx < RPB * PARAM; idx += 256)
        sval[idx >> 7][idx & 127] = val[row0 * PARAM + idx];
    __syncthreads();

    const int r = tid >> 6;          // 0..3 local row
    const int j = tid & 63;          // 0..63 channel
    float accT = 0.f, accB = 0.f;
    #pragma unroll 8
    for (int p = 0; p < PARAM; ++p) {
        const float v = sval[r][p];
        accT = fmaf(v, M1[p * I1 + j],           accT);
        accB = fmaf(v, M1[(PARAM + p) * I1 + j], accB);
    }
    const float sg = g1[j] * rsqrtf(v1[j] + EPS);
    const int row = row0 + r;
    g_A[row * I1 + j] = (accT - accB) * sg + (B1[j] - m1[j]) * sg + b1[j];
    g_C[row * I1 + j] = accB * sg;
}

// ---------------------------------------------------------------------------
// Kernel 2: sparse pair MLP. One block per 4 rows, 256 threads.
// Flat row-pure group list; cheap register metadata; float4 h1 build.
// ---------------------------------------------------------------------------
__global__ __launch_bounds__(256, 2) void pair_kernel(
    const float* __restrict__ mat, const float* __restrict__ val,
    float* __restrict__ out)
{
    extern __shared__ __align__(16) float dyn[];
    float* sM2T = dyn + DYN_M2T_OFF;            // [I2][M2_PAD]
    float* sM3T = dyn + DYN_M3T_OFF;            // [PK][M3_PAD]
    float* sH1  = dyn + DYN_H1_OFF;             // [TOTP][I1]

    __shared__ __align__(16) float sH2[8][GROUP][I2];
    __shared__ __align__(16) float sA[RPB][I1];
    __shared__ float c2s[I2], c3s[PK];
    __shared__ float sSum[RPB][PK];
    __shared__ int   sY[RPB][MAXP];
    __shared__ float sW[RPB][MAXP];
    __shared__ int   sCnt[RPB];
    __shared__ int   sFlatY[TOTP];
    __shared__ float sFlatW[TOTP];
    __shared__ int   sGrpRow[TOTP / GROUP];

    const int tid  = threadIdx.x;
    const int warp = tid >> 5;
    const int lane = tid & 31;
    const int row0 = blockIdx.x * RPB;
    const int b    = row0 >> 8;

    // --- prologue: float4 copies of pre-folded weights ---
    {
        const float4* s2 = (const float4*)g_M2T;
        float4*       d2 = (float4*)sM2T;
        for (int i = tid; i < (I2 * M2_PAD) / 4; i += 256) d2[i] = s2[i];
        const float4* s3 = (const float4*)g_M3T;
        float4*       d3 = (float4*)sM3T;
        for (int i = tid; i < (PK * M3_PAD) / 4; i += 256) d3[i] = s3[i];
    }
    if (tid < I2) c2s[tid] = g_c2[tid];
    if (tid < PK) c3s[tid] = g_c3[tid];
    for (int idx = tid; idx < RPB * I1; idx += 256)
        sA[idx >> 6][idx & 63] = g_A[(row0 + (idx >> 6)) * I1 + (idx & 63)];
    for (int idx = tid; idx < RPB * PK; idx += 256)
        sSum[idx / PK][idx % PK] = 0.f;
    if (tid < RPB) sCnt[tid] = 0;
    __syncthreads();

    // --- compact nonzeros of the 4 mat rows ---
    {
        const float* mbase = mat + row0 * GS;
        #pragma unroll
        for (int e = tid; e < RPB * GS; e += 256) {
            const float w = mbase[e];
            if (w != 0.f) {
                const int r = e >> 8;
                const int y = e & 255;
                const int idx = atomicAdd(&sCnt[r], 1);
                if (idx < MAXP) { sY[r][idx] = y; sW[r][idx] = w; }
            }
        }
    }
    __syncthreads();

    // --- metadata in registers (every thread, no serial phase) ---
    int cc[RPB], off[RPB];
    int tot = 0;
    #pragma unroll
    for (int r = 0; r < RPB; ++r) {
        int c  = min(sCnt[r], MAXP);
        int pc = (c + GROUP - 1) & ~(GROUP - 1);
        if (tot + pc > TOTP) pc = TOTP - tot;   // both multiples of 4
        if (c > pc) c = pc;
        off[r] = tot; cc[r] = c;
        tot += pc;
    }
    const int nG = tot >> 2;

    // --- tiny flat-list phase: thread p < tot writes (y, w, groupRow) ---
    if (tid < tot) {
        const int p = tid;
        const int r = (p >= off[1]) + (p >= off[2]) + (p >= off[3]);
        const int lp = p - off[r];
        const int ok = lp < cc[r];
        sFlatY[p] = ok ? sY[r][lp] : 0;
        sFlatW[p] = ok ? sW[r][lp] : 0.f;
        if ((p & 3) == 0) sGrpRow[p >> 2] = r;
    }
    __syncthreads();

    // --- build ALL h1 vectors in one float4 phase ---
    for (int idx = tid; idx < tot * (I1 / 4); idx += 256) {
        const int p = idx >> 4;          // pair
        const int q = idx & 15;          // float4 index within row
        const int r = sGrpRow[p >> 2];
        const int y = sFlatY[p];
        const float4 cv = ((const float4*)(g_C + (b * GS + y) * I1))[q];
        const float4 av = ((const float4*)(sA[r]))[q];
        float4 h;
        h.x = fmaxf(av.x + cv.x, 0.f);
        h.y = fmaxf(av.y + cv.y, 0.f);
        h.z = fmaxf(av.z + cv.z, 0.f);
        h.w = fmaxf(av.w + cv.w, 0.f);
        ((float4*)(sH1 + p * I1))[q] = h;
    }
    __syncthreads();

    // --- mainloop: warps stride over ALL groups; flush accs on row change ---
    float acc0 = 0.f, acc1 = 0.f, acc2 = 0.f;
    int curR = -1;

    for (int g = warp; g < nG; g += 8) {
        const int r = sGrpRow[g];
        if (r != curR) {
            if (curR >= 0) {
                atomicAdd(&sSum[curR][lane],      acc0);
                atomicAdd(&sSum[curR][lane + 32], acc1);
                atomicAdd(&sSum[curR][lane + 64], acc2);
            }
            curR = r;
            acc0 = acc1 = acc2 = 0.f;
        }
        const int p0 = g * GROUP;

        // ---- h2 for 4 pairs: each weight float4 loaded once ----
        float h0a = c2s[lane], h1a = h0a, h2a = h0a, h3a = h0a;
        const float4* wv = (const float4*)(sM2T + lane * M2_PAD);
        const float4* v0 = (const float4*)(sH1 + (p0 + 0) * I1);
        const float4* v1 = (const float4*)(sH1 + (p0 + 1) * I1);
        const float4* v2 = (const float4*)(sH1 + (p0 + 2) * I1);
        const float4* v3 = (const float4*)(sH1 + (p0 + 3) * I1);
        #pragma unroll
        for (int q = 0; q < I1 / 4; ++q) {
            const float4 w = wv[q];
            const float4 a = v0[q];
            const float4 bb = v1[q];
            const float4 c = v2[q];
            const float4 d = v3[q];
            h0a = fmaf(a.x,  w.x, h0a); h0a = fmaf(a.y,  w.y, h0a);
            h0a = fmaf(a.z,  w.z, h0a); h0a = fmaf(a.w,  w.w, h0a);
            h1a = fmaf(bb.x, w.x, h1a); h1a = fmaf(bb.y, w.y, h1a);
            h1a = fmaf(bb.z, w.z, h1a); h1a = fmaf(bb.w, w.w, h1a);
            h2a = fmaf(c.x,  w.x, h2a); h2a = fmaf(c.y,  w.y, h2a);
            h2a = fmaf(c.z,  w.z, h2a); h2a = fmaf(c.w,  w.w, h2a);
            h3a = fmaf(d.x,  w.x, h3a); h3a = fmaf(d.y,  w.y, h3a);
            h3a = fmaf(d.z,  w.z, h3a); h3a = fmaf(d.w,  w.w, h3a);
        }
        sH2[warp][0][lane] = fmaxf(h0a, 0.f);
        sH2[warp][1][lane] = fmaxf(h1a, 0.f);
        sH2[warp][2][lane] = fmaxf(h2a, 0.f);
        sH2[warp][3][lane] = fmaxf(h3a, 0.f);
        __syncwarp();

        // ---- h3 for 4 pairs x 3 k-slices ----
        float t00 = c3s[lane], t01 = t00, t02 = t00, t03 = t00;
        float t10 = c3s[lane + 32], t11 = t10, t12 = t10, t13 = t10;
        float t20 = c3s[lane + 64], t21 = t20, t22 = t20, t23 = t20;
        const float4* w0 = (const float4*)(sM3T + lane * M3_PAD);
        const float4* w1 = (const float4*)(sM3T + (lane + 32) * M3_PAD);
        const float4* w2 = (const float4*)(sM3T + (lane + 64) * M3_PAD);
        const float4* u0 = (const float4*)sH2[warp][0];
        const float4* u1 = (const float4*)sH2[warp][1];
        const float4* u2 = (const float4*)sH2[warp][2];
        const float4* u3 = (const float4*)sH2[warp][3];
        #pragma unroll
        for (int q = 0; q < I2 / 4; ++q) {
            const float4 a = w0[q];
            const float4 c = w1[q];
            const float4 d = w2[q];
            const float4 h0 = u0[q];
            const float4 h1 = u1[q];
            const float4 h2 = u2[q];
            const float4 h3 = u3[q];
            t00 = fmaf(h0.x, a.x, t00); t00 = fmaf(h0.y, a.y, t00);
            t00 = fmaf(h0.z, a.z, t00); t00 = fmaf(h0.w, a.w, t00);
            t01 = fmaf(h1.x, a.x, t01); t01 = fmaf(h1.y, a.y, t01);
            t01 = fmaf(h1.z, a.z, t01); t01 = fmaf(h1.w, a.w, t01);
            t02 = fmaf(h2.x, a.x, t02); t02 = fmaf(h2.y, a.y, t02);
            t02 = fmaf(h2.z, a.z, t02); t02 = fmaf(h2.w, a.w, t02);
            t03 = fmaf(h3.x, a.x, t03); t03 = fmaf(h3.y, a.y, t03);
            t03 = fmaf(h3.z, a.z, t03); t03 = fmaf(h3.w, a.w, t03);
            t10 = fmaf(h0.x, c.x, t10); t10 = fmaf(h0.y, c.y, t10);
            t10 = fmaf(h0.z, c.z, t10); t10 = fmaf(h0.w, c.w, t10);
            t11 = fmaf(h1.x, c.x, t11); t11 = fmaf(h1.y, c.y, t11);
            t11 = fmaf(h1.z, c.z, t11); t11 = fmaf(h1.w, c.w, t11);
            t12 = fmaf(h2.x, c.x, t12); t12 = fmaf(h2.y, c.y, t12);
            t12 = fmaf(h2.z, c.z, t12); t12 = fmaf(h2.w, c.w, t12);
            t13 = fmaf(h3.x, c.x, t13); t13 = fmaf(h3.y, c.y, t13);
            t13 = fmaf(h3.z, c.z, t13); t13 = fmaf(h3.w, c.w, t13);
            t20 = fmaf(h0.x, d.x, t20); t20 = fmaf(h0.y, d.y, t20);
            t20 = fmaf(h0.z, d.z, t20); t20 = fmaf(h0.w, d.w, t20);
            t21 = fmaf(h1.x, d.x, t21); t21 = fmaf(h1.y, d.y, t21);
            t21 = fmaf(h1.z, d.z, t21); t21 = fmaf(h1.w, d.w, t21);
            t22 = fmaf(h2.x, d.x, t22); t22 = fmaf(h2.y, d.y, t22);
            t22 = fmaf(h2.z, d.z, t22); t22 = fmaf(h2.w, d.w, t22);
            t23 = fmaf(h3.x, d.x, t23); t23 = fmaf(h3.y, d.y, t23);
            t23 = fmaf(h3.z, d.z, t23); t23 = fmaf(h3.w, d.w, t23);
        }
        const float wg0 = sFlatW[p0 + 0];
        const float wg1 = sFlatW[p0 + 1];
        const float wg2 = sFlatW[p0 + 2];
        const float wg3 = sFlatW[p0 + 3];
        acc0 = fmaf(wg0, fmaxf(t00, 0.f), acc0);
        acc0 = fmaf(wg1, fmaxf(t01, 0.f), acc0);
        acc0 = fmaf(wg2, fmaxf(t02, 0.f), acc0);
        acc0 = fmaf(wg3, fmaxf(t03, 0.f), acc0);
        acc1 = fmaf(wg0, fmaxf(t10, 0.f), acc1);
        acc1 = fmaf(wg1, fmaxf(t11, 0.f), acc1);
        acc1 = fmaf(wg2, fmaxf(t12, 0.f), acc1);
        acc1 = fmaf(wg3, fmaxf(t13, 0.f), acc1);
        acc2 = fmaf(wg0, fmaxf(t20, 0.f), acc2);
        acc2 = fmaf(wg1, fmaxf(t21, 0.f), acc2);
        acc2 = fmaf(wg2, fmaxf(t22, 0.f), acc2);
        acc2 = fmaf(wg3, fmaxf(t23, 0.f), acc2);
        __syncwarp();   // protect sH2[warp] before next group's write
    }
    if (curR >= 0) {
        atomicAdd(&sSum[curR][lane],      acc0);
        atomicAdd(&sSum[curR][lane + 32], acc1);
        atomicAdd(&sSum[curR][lane + 64], acc2);
    }
    __syncthreads();

    // --- output: 4 rows x [con(32) | clip(sum/16)(96)] ---
    for (int idx = tid; idx < RPB * PARAM; idx += 256) {
        const int r = idx >> 7;
        const int k = idx & 127;
        const int row = row0 + r;
        float o;
        if (k < KC) o = val[row * PARAM + k];
        else {
            const float s = sSum[r][k - KC] * (1.0f / 16.0f);
            o = fminf(fmaxf(s, -1.f), 1.f);
        }
        out[row * PARAM + k] = o;
    }
}

// ---------------------------------------------------------------------------
extern "C" void kernel_launch(void* const* d_in, const int* in_sizes, int n_in,
                              void* d_out, int out_size)
{
    const float* mat = (const float*)d_in[0];
    const float* val = (const float*)d_in[1];
    const float* M1  = (const float*)d_in[2];
    const float* B1  = (const float*)d_in[3];
    const float* M2  = (const float*)d_in[4];
    const float* B2  = (const float*)d_in[5];
    const float* M3  = (const float*)d_in[6];
    const float* B3  = (const float*)d_in[7];
    const float* g1  = (const float*)d_in[8];
    const float* b1  = (const float*)d_in[9];
    const float* m1  = (const float*)d_in[10];
    const float* v1  = (const float*)d_in[11];
    const float* g2  = (const float*)d_in[12];
    const float* b2  = (const float*)d_in[13];
    const float* m2  = (const float*)d_in[14];
    const float* v2  = (const float*)d_in[15];
    const float* g3  = (const float*)d_in[16];
    const float* b3  = (const float*)d_in[17];
    const float* m3  = (const float*)d_in[18];
    const float* v3  = (const float*)d_in[19];
    float* out = (float*)d_out;

    static int configured = 0;
    if (!configured) {
        cudaFuncSetAttribute(pair_kernel,
                             cudaFuncAttributeMaxDynamicSharedMemorySize,
                             DYN_BYTES);
        configured = 1;
    }

    precompute_kernel<<<NROWS / RPB + 1, 256>>>(val, M1, B1, g1, b1, m1, v1,
                                                M2, B2, M3, B3,
                                                g2, b2, m2, v2, g3, b3, m3, v3);
    pair_kernel<<<NROWS / RPB, 256, DYN_BYTES>>>(mat, val, out);
}

// round 15
// speedup vs baseline: 1.7395x; 1.1168x over previous
#include <cuda_runtime.h>

#define GS      256
#define PARAM   128
#define I1      64
#define I2      32
#define PK      96
#define KC      32
#define BATCH   4
#define NROWS   (BATCH * GS)   // 1024
#define EPS     1e-3f

#define M2_PAD  68             // padded row length for sM2T[i][j]
#define M3_PAD  36             // padded row length for sM3T[k][i]
#define MAXP    48             // per-row cap on stored nonzeros (mean 16, 8 sigma)
#define RPB     4              // rows per block
#define GROUP   4              // pairs per warp-group (weight-load amortization)
#define TOTP    128            // cap on padded pairs per block

// Dynamic smem layout (floats): [ sM2T | sM3T | sH1 ]
#define DYN_M2T_OFF  0
#define DYN_M3T_OFF  (I2 * M2_PAD)                    // 2176
#define DYN_H1_OFF   (DYN_M3T_OFF + PK * M3_PAD)      // 5632
#define DYN_FLOATS   (DYN_H1_OFF + TOTP * I1)         // 13824
#define DYN_BYTES    (DYN_FLOATS * 4)                 // 55296 B

// Scratch (allocation-free rule: __device__ globals). 16B-aligned for float4 access.
__device__ __align__(16) float g_A[NROWS * I1];     // folded A'' (BN1 affine applied)
__device__ __align__(16) float g_C[NROWS * I1];     // C' = val@M1bot * sg1
__device__ __align__(16) float g_M2T[I2 * M2_PAD];  // BN2-folded, transposed: [i][j]
__device__ __align__(16) float g_M3T[PK * M3_PAD];  // BN3-folded, transposed: [k][i]
__device__ float g_c2[I2];
__device__ float g_c3[PK];

// ---------------------------------------------------------------------------
// Kernel 1: precompute A''/C' for 4 rows per block (blocks 0..255)
//           + one extra block (256) folding BN2/BN3 into transposed weights
// ---------------------------------------------------------------------------
__global__ __launch_bounds__(256) void precompute_kernel(
    const float* __restrict__ val,
    const float* __restrict__ M1,   // (2*PARAM, I1) row-major
    const float* __restrict__ B1,
    const float* __restrict__ g1, const float* __restrict__ b1,
    const float* __restrict__ m1, const float* __restrict__ v1,
    const float* __restrict__ M2,  const float* __restrict__ B2,
    const float* __restrict__ M3,  const float* __restrict__ B3,
    const float* __restrict__ g2,  const float* __restrict__ b2,
    const float* __restrict__ m2,  const float* __restrict__ v2,
    const float* __restrict__ g3,  const float* __restrict__ b3,
    const float* __restrict__ m3,  const float* __restrict__ v3)
{
    const int tid = threadIdx.x;

    if (blockIdx.x == NROWS / RPB) {
        __shared__ float sg2[I2], sg3[PK];
        if (tid < I2) {
            const float s = g2[tid] * rsqrtf(v2[tid] + EPS);
            sg2[tid] = s;
            g_c2[tid] = (B2[tid] - m2[tid]) * s + b2[tid];
        }
        if (tid < PK) {
            const float s = g3[tid] * rsqrtf(v3[tid] + EPS);
            sg3[tid] = s;
            g_c3[tid] = (B3[tid] - m3[tid]) * s + b3[tid];
        }
        __syncthreads();
        for (int idx = tid; idx < I2 * I1; idx += 256) {
            const int i  = idx >> 6;
            const int jj = idx & 63;
            g_M2T[i * M2_PAD + jj] = M2[jj * I2 + i] * sg2[i];
        }
        for (int idx = tid; idx < PK * I2; idx += 256) {
            const int k = idx >> 5;
            const int i = idx & 31;
            g_M3T[k * M3_PAD + i] = M3[i * PK + k] * sg3[k];
        }
        return;
    }

    __shared__ float sval[RPB][PARAM];
    const int row0 = blockIdx.x * RPB;
    for (int idx = tid; idx < RPB * PARAM; idx += 256)
        sval[idx >> 7][idx & 127] = val[row0 * PARAM + idx];
    __syncthreads();

    const int r = tid >> 6;          // 0..3 local row
    const int j = tid & 63;          // 0..63 channel
    float accT = 0.f, accB = 0.f;
    #pragma unroll 8
    for (int p = 0; p < PARAM; ++p) {
        const float v = sval[r][p];
        accT = fmaf(v, M1[p * I1 + j],           accT);
        accB = fmaf(v, M1[(PARAM + p) * I1 + j], accB);
    }
    const float sg = g1[j] * rsqrtf(v1[j] + EPS);
    const int row = row0 + r;
    g_A[row * I1 + j] = (accT - accB) * sg + (B1[j] - m1[j]) * sg + b1[j];
    g_C[row * I1 + j] = accB * sg;
}

// ---------------------------------------------------------------------------
// Kernel 2: sparse pair MLP. One block per 4 rows, 256 threads, 3 blocks/SM.
// Flat row-pure group list; cheap register metadata; float4 everywhere.
// ---------------------------------------------------------------------------
__global__ __launch_bounds__(256, 3) void pair_kernel(
    const float* __restrict__ mat, const float* __restrict__ val,
    float* __restrict__ out)
{
    extern __shared__ __align__(16) float dyn[];
    float* sM2T = dyn + DYN_M2T_OFF;            // [I2][M2_PAD]
    float* sM3T = dyn + DYN_M3T_OFF;            // [PK][M3_PAD]
    float* sH1  = dyn + DYN_H1_OFF;             // [TOTP][I1]

    __shared__ __align__(16) float sH2[8][GROUP][I2];
    __shared__ __align__(16) float sA[RPB][I1];
    __shared__ float c2s[I2], c3s[PK];
    __shared__ float sSum[RPB][PK];
    __shared__ int   sY[RPB][MAXP];
    __shared__ float sW[RPB][MAXP];
    __shared__ int   sCnt[RPB];
    __shared__ int   sFlatY[TOTP];
    __shared__ float sFlatW[TOTP];
    __shared__ int   sGrpRow[TOTP / GROUP];

    const int tid  = threadIdx.x;
    const int warp = tid >> 5;
    const int lane = tid & 31;
    const int row0 = blockIdx.x * RPB;
    const int b    = row0 >> 8;

    // --- phase 0: trivial init only, so heavy phases below can overlap ---
    if (tid < RPB) sCnt[tid] = 0;
    __syncthreads();

    // --- phase 1: weight copies + constants + A load + compaction together ---
    {
        const float4* s2 = (const float4*)g_M2T;
        float4*       d2 = (float4*)sM2T;
        for (int i = tid; i < (I2 * M2_PAD) / 4; i += 256) d2[i] = s2[i];
        const float4* s3 = (const float4*)g_M3T;
        float4*       d3 = (float4*)sM3T;
        for (int i = tid; i < (PK * M3_PAD) / 4; i += 256) d3[i] = s3[i];
    }
    if (tid < I2) c2s[tid] = g_c2[tid];
    if (tid < PK) c3s[tid] = g_c3[tid];
    for (int idx = tid; idx < RPB * I1; idx += 256)
        sA[idx >> 6][idx & 63] = g_A[(row0 + (idx >> 6)) * I1 + (idx & 63)];
    for (int idx = tid; idx < RPB * PK; idx += 256)
        sSum[idx / PK][idx % PK] = 0.f;
    // compaction: float4 loads of the 4 mat rows (1024 floats = 256 float4)
    {
        const float4* mbase = (const float4*)(mat + row0 * GS);
        const float4 mv = mbase[tid];
        const int e0 = tid * 4;
        const int r  = e0 >> 8;
        #pragma unroll
        for (int s = 0; s < 4; ++s) {
            const float w = (s == 0) ? mv.x : (s == 1) ? mv.y : (s == 2) ? mv.z : mv.w;
            if (w != 0.f) {
                const int idx = atomicAdd(&sCnt[r], 1);
                if (idx < MAXP) { sY[r][idx] = (e0 + s) & 255; sW[r][idx] = w; }
            }
        }
    }
    __syncthreads();

    // --- metadata in registers (every thread, no serial phase) ---
    int cc[RPB], off[RPB];
    int tot = 0;
    #pragma unroll
    for (int r = 0; r < RPB; ++r) {
        int c  = min(sCnt[r], MAXP);
        int pc = (c + GROUP - 1) & ~(GROUP - 1);
        if (tot + pc > TOTP) pc = TOTP - tot;   // both multiples of 4
        if (c > pc) c = pc;
        off[r] = tot; cc[r] = c;
        tot += pc;
    }
    const int nG = tot >> 2;

    // --- tiny flat-list phase: thread p < tot writes (y, w, groupRow) ---
    if (tid < tot) {
        const int p = tid;
        const int r = (p >= off[1]) + (p >= off[2]) + (p >= off[3]);
        const int lp = p - off[r];
        const int ok = lp < cc[r];
        sFlatY[p] = ok ? sY[r][lp] : 0;
        sFlatW[p] = ok ? sW[r][lp] : 0.f;
        if ((p & 3) == 0) sGrpRow[p >> 2] = r;
    }
    __syncthreads();

    // --- build ALL h1 vectors in one float4 phase ---
    for (int idx = tid; idx < tot * (I1 / 4); idx += 256) {
        const int p = idx >> 4;          // pair
        const int q = idx & 15;          // float4 index within row
        const int r = sGrpRow[p >> 2];
        const int y = sFlatY[p];
        const float4 cv = ((const float4*)(g_C + (b * GS + y) * I1))[q];
        const float4 av = ((const float4*)(sA[r]))[q];
        float4 h;
        h.x = fmaxf(av.x + cv.x, 0.f);
        h.y = fmaxf(av.y + cv.y, 0.f);
        h.z = fmaxf(av.z + cv.z, 0.f);
        h.w = fmaxf(av.w + cv.w, 0.f);
        ((float4*)(sH1 + p * I1))[q] = h;
    }
    __syncthreads();

    // --- mainloop: warps stride over ALL groups; flush accs on row change ---
    float acc0 = 0.f, acc1 = 0.f, acc2 = 0.f;
    int curR = -1;

    for (int g = warp; g < nG; g += 8) {
        const int r = sGrpRow[g];
        if (r != curR) {
            if (curR >= 0) {
                atomicAdd(&sSum[curR][lane],      acc0);
                atomicAdd(&sSum[curR][lane + 32], acc1);
                atomicAdd(&sSum[curR][lane + 64], acc2);
            }
            curR = r;
            acc0 = acc1 = acc2 = 0.f;
        }
        const int p0 = g * GROUP;

        // ---- h2 for 4 pairs: each weight float4 loaded once ----
        float h0a = c2s[lane], h1a = h0a, h2a = h0a, h3a = h0a;
        const float4* wv = (const float4*)(sM2T + lane * M2_PAD);
        const float4* v0 = (const float4*)(sH1 + (p0 + 0) * I1);
        const float4* v1 = (const float4*)(sH1 + (p0 + 1) * I1);
        const float4* v2 = (const float4*)(sH1 + (p0 + 2) * I1);
        const float4* v3 = (const float4*)(sH1 + (p0 + 3) * I1);
        #pragma unroll
        for (int q = 0; q < I1 / 4; ++q) {
            const float4 w = wv[q];
            const float4 a = v0[q];
            const float4 bb = v1[q];
            const float4 c = v2[q];
            const float4 d = v3[q];
            h0a = fmaf(a.x,  w.x, h0a); h0a = fmaf(a.y,  w.y, h0a);
            h0a = fmaf(a.z,  w.z, h0a); h0a = fmaf(a.w,  w.w, h0a);
            h1a = fmaf(bb.x, w.x, h1a); h1a = fmaf(bb.y, w.y, h1a);
            h1a = fmaf(bb.z, w.z, h1a); h1a = fmaf(bb.w, w.w, h1a);
            h2a = fmaf(c.x,  w.x, h2a); h2a = fmaf(c.y,  w.y, h2a);
            h2a = fmaf(c.z,  w.z, h2a); h2a = fmaf(c.w,  w.w, h2a);
            h3a = fmaf(d.x,  w.x, h3a); h3a = fmaf(d.y,  w.y, h3a);
            h3a = fmaf(d.z,  w.z, h3a); h3a = fmaf(d.w,  w.w, h3a);
        }
        sH2[warp][0][lane] = fmaxf(h0a, 0.f);
        sH2[warp][1][lane] = fmaxf(h1a, 0.f);
        sH2[warp][2][lane] = fmaxf(h2a, 0.f);
        sH2[warp][3][lane] = fmaxf(h3a, 0.f);
        __syncwarp();

        // ---- h3 for 4 pairs x 3 k-slices ----
        float t00 = c3s[lane], t01 = t00, t02 = t00, t03 = t00;
        float t10 = c3s[lane + 32], t11 = t10, t12 = t10, t13 = t10;
        float t20 = c3s[lane + 64], t21 = t20, t22 = t20, t23 = t20;
        const float4* w0 = (const float4*)(sM3T + lane * M3_PAD);
        const float4* w1 = (const float4*)(sM3T + (lane + 32) * M3_PAD);
        const float4* w2 = (const float4*)(sM3T + (lane + 64) * M3_PAD);
        const float4* u0 = (const float4*)sH2[warp][0];
        const float4* u1 = (const float4*)sH2[warp][1];
        const float4* u2 = (const float4*)sH2[warp][2];
        const float4* u3 = (const float4*)sH2[warp][3];
        #pragma unroll
        for (int q = 0; q < I2 / 4; ++q) {
            const float4 a = w0[q];
            const float4 c = w1[q];
            const float4 d = w2[q];
            const float4 h0 = u0[q];
            const float4 h1 = u1[q];
            const float4 h2 = u2[q];
            const float4 h3 = u3[q];
            t00 = fmaf(h0.x, a.x, t00); t00 = fmaf(h0.y, a.y, t00);
            t00 = fmaf(h0.z, a.z, t00); t00 = fmaf(h0.w, a.w, t00);
            t01 = fmaf(h1.x, a.x, t01); t01 = fmaf(h1.y, a.y, t01);
            t01 = fmaf(h1.z, a.z, t01); t01 = fmaf(h1.w, a.w, t01);
            t02 = fmaf(h2.x, a.x, t02); t02 = fmaf(h2.y, a.y, t02);
            t02 = fmaf(h2.z, a.z, t02); t02 = fmaf(h2.w, a.w, t02);
            t03 = fmaf(h3.x, a.x, t03); t03 = fmaf(h3.y, a.y, t03);
            t03 = fmaf(h3.z, a.z, t03); t03 = fmaf(h3.w, a.w, t03);
            t10 = fmaf(h0.x, c.x, t10); t10 = fmaf(h0.y, c.y, t10);
            t10 = fmaf(h0.z, c.z, t10); t10 = fmaf(h0.w, c.w, t10);
            t11 = fmaf(h1.x, c.x, t11); t11 = fmaf(h1.y, c.y, t11);
            t11 = fmaf(h1.z, c.z, t11); t11 = fmaf(h1.w, c.w, t11);
            t12 = fmaf(h2.x, c.x, t12); t12 = fmaf(h2.y, c.y, t12);
            t12 = fmaf(h2.z, c.z, t12); t12 = fmaf(h2.w, c.w, t12);
            t13 = fmaf(h3.x, c.x, t13); t13 = fmaf(h3.y, c.y, t13);
            t13 = fmaf(h3.z, c.z, t13); t13 = fmaf(h3.w, c.w, t13);
            t20 = fmaf(h0.x, d.x, t20); t20 = fmaf(h0.y, d.y, t20);
            t20 = fmaf(h0.z, d.z, t20); t20 = fmaf(h0.w, d.w, t20);
            t21 = fmaf(h1.x, d.x, t21); t21 = fmaf(h1.y, d.y, t21);
            t21 = fmaf(h1.z, d.z, t21); t21 = fmaf(h1.w, d.w, t21);
            t22 = fmaf(h2.x, d.x, t22); t22 = fmaf(h2.y, d.y, t22);
            t22 = fmaf(h2.z, d.z, t22); t22 = fmaf(h2.w, d.w, t22);
            t23 = fmaf(h3.x, d.x, t23); t23 = fmaf(h3.y, d.y, t23);
            t23 = fmaf(h3.z, d.z, t23); t23 = fmaf(h3.w, d.w, t23);
        }
        const float wg0 = sFlatW[p0 + 0];
        const float wg1 = sFlatW[p0 + 1];
        const float wg2 = sFlatW[p0 + 2];
        const float wg3 = sFlatW[p0 + 3];
        acc0 = fmaf(wg0, fmaxf(t00, 0.f), acc0);
        acc0 = fmaf(wg1, fmaxf(t01, 0.f), acc0);
        acc0 = fmaf(wg2, fmaxf(t02, 0.f), acc0);
        acc0 = fmaf(wg3, fmaxf(t03, 0.f), acc0);
        acc1 = fmaf(wg0, fmaxf(t10, 0.f), acc1);
        acc1 = fmaf(wg1, fmaxf(t11, 0.f), acc1);
        acc1 = fmaf(wg2, fmaxf(t12, 0.f), acc1);
        acc1 = fmaf(wg3, fmaxf(t13, 0.f), acc1);
        acc2 = fmaf(wg0, fmaxf(t20, 0.f), acc2);
        acc2 = fmaf(wg1, fmaxf(t21, 0.f), acc2);
        acc2 = fmaf(wg2, fmaxf(t22, 0.f), acc2);
        acc2 = fmaf(wg3, fmaxf(t23, 0.f), acc2);
        __syncwarp();   // protect sH2[warp] before next group's write
    }
    if (curR >= 0) {
        atomicAdd(&sSum[curR][lane],      acc0);
        atomicAdd(&sSum[curR][lane + 32], acc1);
        atomicAdd(&sSum[curR][lane + 64], acc2);
    }
    __syncthreads();

    // --- output: 4 rows x [con(32) | clip(sum/16)(96)] ---
    for (int idx = tid; idx < RPB * PARAM; idx += 256) {
        const int r = idx >> 7;
        const int k = idx & 127;
        const int row = row0 + r;
        float o;
        if (k < KC) o = val[row * PARAM + k];
        else {
            const float s = sSum[r][k - KC] * (1.0f / 16.0f);
            o = fminf(fmaxf(s, -1.f), 1.f);
        }
        out[row * PARAM + k] = o;
    }
}

// ---------------------------------------------------------------------------
extern "C" void kernel_launch(void* const* d_in, const int* in_sizes, int n_in,
                              void* d_out, int out_size)
{
    const float* mat = (const float*)d_in[0];
    const float* val = (const float*)d_in[1];
    const float* M1  = (const float*)d_in[2];
    const float* B1  = (const float*)d_in[3];
    const float* M2  = (const float*)d_in[4];
    const float* B2  = (const float*)d_in[5];
    const float* M3  = (const float*)d_in[6];
    const float* B3  = (const float*)d_in[7];
    const float* g1  = (const float*)d_in[8];
    const float* b1  = (const float*)d_in[9];
    const float* m1  = (const float*)d_in[10];
    const float* v1  = (const float*)d_in[11];
    const float* g2  = (const float*)d_in[12];
    const float* b2  = (const float*)d_in[13];
    const float* m2  = (const float*)d_in[14];
    const float* v2  = (const float*)d_in[15];
    const float* g3  = (const float*)d_in[16];
    const float* b3  = (const float*)d_in[17];
    const float* m3  = (const float*)d_in[18];
    const float* v3  = (const float*)d_in[19];
    float* out = (float*)d_out;

    static int configured = 0;
    if (!configured) {
        cudaFuncSetAttribute(pair_kernel,
                             cudaFuncAttributeMaxDynamicSharedMemorySize,
                             DYN_BYTES);
        configured = 1;
    }

    precompute_kernel<<<NROWS / RPB + 1, 256>>>(val, M1, B1, g1, b1, m1, v1,
                                                M2, B2, M3, B3,
                                                g2, b2, m2, v2, g3, b3, m3, v3);
    pair_kernel<<<NROWS / RPB, 256, DYN_BYTES>>>(mat, val, out);
}

// round 16
// speedup vs baseline: 1.7559x; 1.0094x over previous
#include <cuda_runtime.h>

#define GS      256
#define PARAM   128
#define I1      64
#define I2      32
#define PK      96
#define KC      32
#define BATCH   4
#define NROWS   (BATCH * GS)   // 1024
#define EPS     1e-3f

#define M2_PAD  68             // padded row length for sM2T[i][j]
#define M3_PAD  36             // padded row length for sM3T[k][i]
#define MAXP    48             // per-row cap on stored nonzeros (mean 16, 8 sigma)
#define RPB     2              // rows per block  (grid 512 -> fills the 148 SMs)
#define GROUP   4              // pairs per warp-group (weight-load amortization)
#define TOTP    64             // cap on padded pairs per block (2 rows x 48 max)

// Dynamic smem layout (floats): [ sM2T | sM3T | sH1 ]
#define DYN_M2T_OFF  0
#define DYN_M3T_OFF  (I2 * M2_PAD)                    // 2176
#define DYN_H1_OFF   (DYN_M3T_OFF + PK * M3_PAD)      // 5632
#define DYN_FLOATS   (DYN_H1_OFF + TOTP * I1)         // 9728
#define DYN_BYTES    (DYN_FLOATS * 4)                 // 38912 B

// Scratch (allocation-free rule: __device__ globals). 16B-aligned for float4 access.
__device__ __align__(16) float g_A[NROWS * I1];     // folded A'' (BN1 affine applied)
__device__ __align__(16) float g_C[NROWS * I1];     // C' = val@M1bot * sg1
__device__ __align__(16) float g_M2T[I2 * M2_PAD];  // BN2-folded, transposed: [i][j]
__device__ __align__(16) float g_M3T[PK * M3_PAD];  // BN3-folded, transposed: [k][i]
__device__ float g_c2[I2];
__device__ float g_c3[PK];

// ---------------------------------------------------------------------------
// Kernel 1: precompute A''/C' for 4 rows per block (blocks 0..255)
//           + one extra block (256) folding BN2/BN3 into transposed weights
// ---------------------------------------------------------------------------
#define PRE_RPB 4
__global__ __launch_bounds__(256) void precompute_kernel(
    const float* __restrict__ val,
    const float* __restrict__ M1,   // (2*PARAM, I1) row-major
    const float* __restrict__ B1,
    const float* __restrict__ g1, const float* __restrict__ b1,
    const float* __restrict__ m1, const float* __restrict__ v1,
    const float* __restrict__ M2,  const float* __restrict__ B2,
    const float* __restrict__ M3,  const float* __restrict__ B3,
    const float* __restrict__ g2,  const float* __restrict__ b2,
    const float* __restrict__ m2,  const float* __restrict__ v2,
    const float* __restrict__ g3,  const float* __restrict__ b3,
    const float* __restrict__ m3,  const float* __restrict__ v3)
{
    const int tid = threadIdx.x;

    if (blockIdx.x == NROWS / PRE_RPB) {
        __shared__ float sg2[I2], sg3[PK];
        if (tid < I2) {
            const float s = g2[tid] * rsqrtf(v2[tid] + EPS);
            sg2[tid] = s;
            g_c2[tid] = (B2[tid] - m2[tid]) * s + b2[tid];
        }
        if (tid < PK) {
            const float s = g3[tid] * rsqrtf(v3[tid] + EPS);
            sg3[tid] = s;
            g_c3[tid] = (B3[tid] - m3[tid]) * s + b3[tid];
        }
        __syncthreads();
        for (int idx = tid; idx < I2 * I1; idx += 256) {
            const int i  = idx >> 6;
            const int jj = idx & 63;
            g_M2T[i * M2_PAD + jj] = M2[jj * I2 + i] * sg2[i];
        }
        for (int idx = tid; idx < PK * I2; idx += 256) {
            const int k = idx >> 5;
            const int i = idx & 31;
            g_M3T[k * M3_PAD + i] = M3[i * PK + k] * sg3[k];
        }
        return;
    }

    __shared__ float sval[PRE_RPB][PARAM];
    const int row0 = blockIdx.x * PRE_RPB;
    for (int idx = tid; idx < PRE_RPB * PARAM; idx += 256)
        sval[idx >> 7][idx & 127] = val[row0 * PARAM + idx];
    __syncthreads();

    const int r = tid >> 6;          // 0..3 local row
    const int j = tid & 63;          // 0..63 channel
    float accT = 0.f, accB = 0.f;
    #pragma unroll 8
    for (int p = 0; p < PARAM; ++p) {
        const float v = sval[r][p];
        accT = fmaf(v, M1[p * I1 + j],           accT);
        accB = fmaf(v, M1[(PARAM + p) * I1 + j], accB);
    }
    const float sg = g1[j] * rsqrtf(v1[j] + EPS);
    const int row = row0 + r;
    g_A[row * I1 + j] = (accT - accB) * sg + (B1[j] - m1[j]) * sg + b1[j];
    g_C[row * I1 + j] = accB * sg;
}

// ---------------------------------------------------------------------------
// Kernel 2: sparse pair MLP. One block per 2 rows, 256 threads, grid 512.
// Flat row-pure group list; cheap register metadata; float4 everywhere.
// ---------------------------------------------------------------------------
__global__ __launch_bounds__(256, 3) void pair_kernel(
    const float* __restrict__ mat, const float* __restrict__ val,
    float* __restrict__ out)
{
    extern __shared__ __align__(16) float dyn[];
    float* sM2T = dyn + DYN_M2T_OFF;            // [I2][M2_PAD]
    float* sM3T = dyn + DYN_M3T_OFF;            // [PK][M3_PAD]
    float* sH1  = dyn + DYN_H1_OFF;             // [TOTP][I1]

    __shared__ __align__(16) float sH2[8][GROUP][I2];
    __shared__ __align__(16) float sA[RPB][I1];
    __shared__ float c2s[I2], c3s[PK];
    __shared__ float sSum[RPB][PK];
    __shared__ int   sY[RPB][MAXP];
    __shared__ float sW[RPB][MAXP];
    __shared__ int   sCnt[RPB];
    __shared__ int   sFlatY[TOTP];
    __shared__ float sFlatW[TOTP];
    __shared__ int   sGrpRow[TOTP / GROUP];

    const int tid  = threadIdx.x;
    const int warp = tid >> 5;
    const int lane = tid & 31;
    const int row0 = blockIdx.x * RPB;
    const int b    = row0 >> 8;

    // --- phase 0: trivial init only, so heavy phases below can overlap ---
    if (tid < RPB) sCnt[tid] = 0;
    __syncthreads();

    // --- phase 1: weight copies + constants + A load + compaction together ---
    {
        const float4* s2 = (const float4*)g_M2T;
        float4*       d2 = (float4*)sM2T;
        for (int i = tid; i < (I2 * M2_PAD) / 4; i += 256) d2[i] = s2[i];
        const float4* s3 = (const float4*)g_M3T;
        float4*       d3 = (float4*)sM3T;
        for (int i = tid; i < (PK * M3_PAD) / 4; i += 256) d3[i] = s3[i];
    }
    if (tid < I2) c2s[tid] = g_c2[tid];
    if (tid < PK) c3s[tid] = g_c3[tid];
    if (tid < RPB * I1)
        sA[tid >> 6][tid & 63] = g_A[(row0 + (tid >> 6)) * I1 + (tid & 63)];
    if (tid < RPB * PK)
        sSum[tid / PK][tid % PK] = 0.f;
    // compaction: float4 loads of the 2 mat rows (512 floats = 128 float4)
    if (tid < (RPB * GS) / 4) {
        const float4* mbase = (const float4*)(mat + row0 * GS);
        const float4 mv = mbase[tid];
        const int e0 = tid * 4;
        const int r  = e0 >> 8;
        #pragma unroll
        for (int s = 0; s < 4; ++s) {
            const float w = (s == 0) ? mv.x : (s == 1) ? mv.y : (s == 2) ? mv.z : mv.w;
            if (w != 0.f) {
                const int idx = atomicAdd(&sCnt[r], 1);
                if (idx < MAXP) { sY[r][idx] = (e0 + s) & 255; sW[r][idx] = w; }
            }
        }
    }
    __syncthreads();

    // --- metadata in registers (every thread, no serial phase) ---
    int cc[RPB], off[RPB];
    int tot = 0;
    #pragma unroll
    for (int r = 0; r < RPB; ++r) {
        int c  = min(sCnt[r], MAXP);
        int pc = (c + GROUP - 1) & ~(GROUP - 1);
        if (tot + pc > TOTP) pc = TOTP - tot;   // both multiples of 4
        if (c > pc) c = pc;
        off[r] = tot; cc[r] = c;
        tot += pc;
    }
    const int nG = tot >> 2;

    // --- tiny flat-list phase: thread p < tot writes (y, w, groupRow) ---
    if (tid < tot) {
        const int p = tid;
        const int r = (p >= off[1]);
        const int lp = p - off[r];
        const int ok = lp < cc[r];
        sFlatY[p] = ok ? sY[r][lp] : 0;
        sFlatW[p] = ok ? sW[r][lp] : 0.f;
        if ((p & 3) == 0) sGrpRow[p >> 2] = r;
    }
    __syncthreads();

    // --- build ALL h1 vectors in one float4 phase ---
    for (int idx = tid; idx < tot * (I1 / 4); idx += 256) {
        const int p = idx >> 4;          // pair
        const int q = idx & 15;          // float4 index within row
        const int r = sGrpRow[p >> 2];
        const int y = sFlatY[p];
        const float4 cv = ((const float4*)(g_C + (b * GS + y) * I1))[q];
        const float4 av = ((const float4*)(sA[r]))[q];
        float4 h;
        h.x = fmaxf(av.x + cv.x, 0.f);
        h.y = fmaxf(av.y + cv.y, 0.f);
        h.z = fmaxf(av.z + cv.z, 0.f);
        h.w = fmaxf(av.w + cv.w, 0.f);
        ((float4*)(sH1 + p * I1))[q] = h;
    }
    __syncthreads();

    // --- mainloop: warps stride over ALL groups; flush accs on row change ---
    float acc0 = 0.f, acc1 = 0.f, acc2 = 0.f;
    int curR = -1;

    for (int g = warp; g < nG; g += 8) {
        const int r = sGrpRow[g];
        if (r != curR) {
            if (curR >= 0) {
                atomicAdd(&sSum[curR][lane],      acc0);
                atomicAdd(&sSum[curR][lane + 32], acc1);
                atomicAdd(&sSum[curR][lane + 64], acc2);
            }
            curR = r;
            acc0 = acc1 = acc2 = 0.f;
        }
        const int p0 = g * GROUP;

        // ---- h2 for 4 pairs: each weight float4 loaded once ----
        float h0a = c2s[lane], h1a = h0a, h2a = h0a, h3a = h0a;
        const float4* wv = (const float4*)(sM2T + lane * M2_PAD);
        const float4* v0 = (const float4*)(sH1 + (p0 + 0) * I1);
        const float4* v1 = (const float4*)(sH1 + (p0 + 1) * I1);
        const float4* v2 = (const float4*)(sH1 + (p0 + 2) * I1);
        const float4* v3 = (const float4*)(sH1 + (p0 + 3) * I1);
        #pragma unroll
        for (int q = 0; q < I1 / 4; ++q) {
            const float4 w = wv[q];
            const float4 a = v0[q];
            const float4 bb = v1[q];
            const float4 c = v2[q];
            const float4 d = v3[q];
            h0a = fmaf(a.x,  w.x, h0a); h0a = fmaf(a.y,  w.y, h0a);
            h0a = fmaf(a.z,  w.z, h0a); h0a = fmaf(a.w,  w.w, h0a);
            h1a = fmaf(bb.x, w.x, h1a); h1a = fmaf(bb.y, w.y, h1a);
            h1a = fmaf(bb.z, w.z, h1a); h1a = fmaf(bb.w, w.w, h1a);
            h2a = fmaf(c.x,  w.x, h2a); h2a = fmaf(c.y,  w.y, h2a);
            h2a = fmaf(c.z,  w.z, h2a); h2a = fmaf(c.w,  w.w, h2a);
            h3a = fmaf(d.x,  w.x, h3a); h3a = fmaf(d.y,  w.y, h3a);
            h3a = fmaf(d.z,  w.z, h3a); h3a = fmaf(d.w,  w.w, h3a);
        }
        sH2[warp][0][lane] = fmaxf(h0a, 0.f);
        sH2[warp][1][lane] = fmaxf(h1a, 0.f);
        sH2[warp][2][lane] = fmaxf(h2a, 0.f);
        sH2[warp][3][lane] = fmaxf(h3a, 0.f);
        __syncwarp();

        // ---- h3 for 4 pairs x 3 k-slices ----
        float t00 = c3s[lane], t01 = t00, t02 = t00, t03 = t00;
        float t10 = c3s[lane + 32], t11 = t10, t12 = t10, t13 = t10;
        float t20 = c3s[lane + 64], t21 = t20, t22 = t20, t23 = t20;
        const float4* w0 = (const float4*)(sM3T + lane * M3_PAD);
        const float4* w1 = (const float4*)(sM3T + (lane + 32) * M3_PAD);
        const float4* w2 = (const float4*)(sM3T + (lane + 64) * M3_PAD);
        const float4* u0 = (const float4*)sH2[warp][0];
        const float4* u1 = (const float4*)sH2[warp][1];
        const float4* u2 = (const float4*)sH2[warp][2];
        const float4* u3 = (const float4*)sH2[warp][3];
        #pragma unroll
        for (int q = 0; q < I2 / 4; ++q) {
            const float4 a = w0[q];
            const float4 c = w1[q];
            const float4 d = w2[q];
            const float4 h0 = u0[q];
            const float4 h1 = u1[q];
            const float4 h2 = u2[q];
            const float4 h3 = u3[q];
            t00 = fmaf(h0.x, a.x, t00); t00 = fmaf(h0.y, a.y, t00);
            t00 = fmaf(h0.z, a.z, t00); t00 = fmaf(h0.w, a.w, t00);
            t01 = fmaf(h1.x, a.x, t01); t01 = fmaf(h1.y, a.y, t01);
            t01 = fmaf(h1.z, a.z, t01); t01 = fmaf(h1.w, a.w, t01);
            t02 = fmaf(h2.x, a.x, t02); t02 = fmaf(h2.y, a.y, t02);
            t02 = fmaf(h2.z, a.z, t02); t02 = fmaf(h2.w, a.w, t02);
            t03 = fmaf(h3.x, a.x, t03); t03 = fmaf(h3.y, a.y, t03);
            t03 = fmaf(h3.z, a.z, t03); t03 = fmaf(h3.w, a.w, t03);
            t10 = fmaf(h0.x, c.x, t10); t10 = fmaf(h0.y, c.y, t10);
            t10 = fmaf(h0.z, c.z, t10); t10 = fmaf(h0.w, c.w, t10);
            t11 = fmaf(h1.x, c.x, t11); t11 = fmaf(h1.y, c.y, t11);
            t11 = fmaf(h1.z, c.z, t11); t11 = fmaf(h1.w, c.w, t11);
            t12 = fmaf(h2.x, c.x, t12); t12 = fmaf(h2.y, c.y, t12);
            t12 = fmaf(h2.z, c.z, t12); t12 = fmaf(h2.w, c.w, t12);
            t13 = fmaf(h3.x, c.x, t13); t13 = fmaf(h3.y, c.y, t13);
            t13 = fmaf(h3.z, c.z, t13); t13 = fmaf(h3.w, c.w, t13);
            t20 = fmaf(h0.x, d.x, t20); t20 = fmaf(h0.y, d.y, t20);
            t20 = fmaf(h0.z, d.z, t20); t20 = fmaf(h0.w, d.w, t20);
            t21 = fmaf(h1.x, d.x, t21); t21 = fmaf(h1.y, d.y, t21);
            t21 = fmaf(h1.z, d.z, t21); t21 = fmaf(h1.w, d.w, t21);
            t22 = fmaf(h2.x, d.x, t22); t22 = fmaf(h2.y, d.y, t22);
            t22 = fmaf(h2.z, d.z, t22); t22 = fmaf(h2.w, d.w, t22);
            t23 = fmaf(h3.x, d.x, t23); t23 = fmaf(h3.y, d.y, t23);
            t23 = fmaf(h3.z, d.z, t23); t23 = fmaf(h3.w, d.w, t23);
        }
        const float wg0 = sFlatW[p0 + 0];
        const float wg1 = sFlatW[p0 + 1];
        const float wg2 = sFlatW[p0 + 2];
        const float wg3 = sFlatW[p0 + 3];
        acc0 = fmaf(wg0, fmaxf(t00, 0.f), acc0);
        acc0 = fmaf(wg1, fmaxf(t01, 0.f), acc0);
        acc0 = fmaf(wg2, fmaxf(t02, 0.f), acc0);
        acc0 = fmaf(wg3, fmaxf(t03, 0.f), acc0);
        acc1 = fmaf(wg0, fmaxf(t10, 0.f), acc1);
        acc1 = fmaf(wg1, fmaxf(t11, 0.f), acc1);
        acc1 = fmaf(wg2, fmaxf(t12, 0.f), acc1);
        acc1 = fmaf(wg3, fmaxf(t13, 0.f), acc1);
        acc2 = fmaf(wg0, fmaxf(t20, 0.f), acc2);
        acc2 = fmaf(wg1, fmaxf(t21, 0.f), acc2);
        acc2 = fmaf(wg2, fmaxf(t22, 0.f), acc2);
        acc2 = fmaf(wg3, fmaxf(t23, 0.f), acc2);
        __syncwarp();   // protect sH2[warp] before next group's write
    }
    if (curR >= 0) {
        atomicAdd(&sSum[curR][lane],      acc0);
        atomicAdd(&sSum[curR][lane + 32], acc1);
        atomicAdd(&sSum[curR][lane + 64], acc2);
    }
    __syncthreads();

    // --- output: 2 rows x [con(32) | clip(sum/16)(96)] = 256 elems ---
    {
        const int r = tid >> 7;
        const int k = tid & 127;
        const int row = row0 + r;
        float o;
        if (k < KC) o = val[row * PARAM + k];
        else {
            const float s = sSum[r][k - KC] * (1.0f / 16.0f);
            o = fminf(fmaxf(s, -1.f), 1.f);
        }
        out[row * PARAM + k] = o;
    }
}

// ---------------------------------------------------------------------------
extern "C" void kernel_launch(void* const* d_in, const int* in_sizes, int n_in,
                              void* d_out, int out_size)
{
    const float* mat = (const float*)d_in[0];
    const float* val = (const float*)d_in[1];
    const float* M1  = (const float*)d_in[2];
    const float* B1  = (const float*)d_in[3];
    const float* M2  = (const float*)d_in[4];
    const float* B2  = (const float*)d_in[5];
    const float* M3  = (const float*)d_in[6];
    const float* B3  = (const float*)d_in[7];
    const float* g1  = (const float*)d_in[8];
    const float* b1  = (const float*)d_in[9];
    const float* m1  = (const float*)d_in[10];
    const float* v1  = (const float*)d_in[11];
    const float* g2  = (const float*)d_in[12];
    const float* b2  = (const float*)d_in[13];
    const float* m2  = (const float*)d_in[14];
    const float* v2  = (const float*)d_in[15];
    const float* g3  = (const float*)d_in[16];
    const float* b3  = (const float*)d_in[17];
    const float* m3  = (const float*)d_in[18];
    const float* v3  = (const float*)d_in[19];
    float* out = (float*)d_out;

    static int configured = 0;
    if (!configured) {
        cudaFuncSetAttribute(pair_kernel,
                             cudaFuncAttributeMaxDynamicSharedMemorySize,
                             DYN_BYTES);
        configured = 1;
    }

    precompute_kernel<<<NROWS / PRE_RPB + 1, 256>>>(val, M1, B1, g1, b1, m1, v1,
                                                    M2, B2, M3, B3,
                                                    g2, b2, m2, v2, g3, b3, m3, v3);
    pair_kernel<<<NROWS / RPB, 256, DYN_BYTES>>>(mat, val, out);
}